// round 16
// baseline (speedup 1.0000x reference)
#include <cuda_runtime.h>
#include <cuda_fp16.h>
#include <math.h>

#define NB 16
#define NA 720
#define ND 1024
#define NH 512
#define NW 512
#define PI_F 3.14159265358979323846f

// Filtered sinogram in fp16: g_v[g2][a][bin] = uint4 record of 8 batches
// (batches 8*g2 .. 8*g2+7, stored as 4 half2). 23.6 MB, L2-resident.
__device__ uint4 g_v[2 * NA * ND];

__device__ __forceinline__ float2 cmulf(float2 a, float2 b) {
    return make_float2(a.x * b.x - a.y * b.y, a.x * b.y + a.y * b.x);
}
__device__ __forceinline__ float2 cadd(float2 a, float2 b) {
    return make_float2(a.x + b.x, a.y + b.y);
}
__device__ __forceinline__ float2 csub(float2 a, float2 b) {
    return make_float2(a.x - b.x, a.y - b.y);
}
__device__ __forceinline__ unsigned int h2_as_u32(__half2 h) {
    return *reinterpret_cast<unsigned int*>(&h);
}
__device__ __forceinline__ __half2 u32_as_h2(unsigned int u) {
    return *reinterpret_cast<__half2*>(&u);
}

// -------------------------------------------------------------------------
// Kernel 1: ramp filter via complex-pair RADIX-4 Stockham FFT (5 fwd + 5
// inv stages instead of 10+10 radix-2: half the barriers/smem passes).
// Filter real & even: FFT(u+iv)*f -> re=filt(u), im=filt(v) exactly.
// Block = (angle a, batch pair m), 256 threads, 4 elements/thread.
// Radix-4 stage (derived by composing two radix-2 Stockham stages,
// verified against the N=4 DFT): s = 4^stage, tid = P*s+q,
//   z[4Ps+q]      = (a0+a2) + (a1+a3)
//   z[4Ps+s+q]    = tw[Ps]  * ((a0-a2) -+ i(a1-a3))   (fwd -, inv +)
//   z[4Ps+2s+q]   = tw[2Ps] * ((a0+a2) - (a1+a3))
//   z[4Ps+3s+q]   = tw[3Ps] * ((a0-a2) +- i(a1-a3))   (fwd +, inv -)
// with tw[k] = exp(-2*pi*i*k/N) (conjugated for inverse).
// -------------------------------------------------------------------------
__global__ __launch_bounds__(256) void fbp_filter_kernel(
    const float* __restrict__ sino, const float* __restrict__ filt)
{
    __shared__ float2 bufA[ND];
    __shared__ float2 bufB[ND];
    __shared__ float2 tw[768];      // exp(-2*pi*i*k/N), k in [0,768)

    const int a = blockIdx.x;
    const int m = blockIdx.y;       // batches 2m, 2m+1
    const int tid = threadIdx.x;    // 0..255

    const float* u = sino + ((size_t)(2 * m) * NA + a) * ND;
    const float* v = sino + ((size_t)(2 * m + 1) * NA + a) * ND;

    #pragma unroll
    for (int e = 0; e < 4; ++e) {
        int i = tid + 256 * e;
        bufA[i] = make_float2(u[i], v[i]);
    }
    #pragma unroll
    for (int k = 0; k < 3; ++k) {
        int i = tid + 256 * k;
        float sv, cv;
        sincosf((-2.0f * PI_F / ND) * (float)i, &sv, &cv);
        tw[i] = make_float2(cv, sv);
    }
    __syncthreads();

    float2* x = bufA;
    float2* y = bufB;

    // Forward FFT: 5 radix-4 stages
    #pragma unroll
    for (int stage = 0; stage < 5; ++stage) {
        const int s  = 1 << (2 * stage);
        const int q  = tid & (s - 1);
        const int ps = tid - q;                 // P*s
        float2 a0 = x[tid];
        float2 a1 = x[tid + 256];
        float2 a2 = x[tid + 512];
        float2 a3 = x[tid + 768];
        float2 t02p = cadd(a0, a2), t02m = csub(a0, a2);
        float2 t13p = cadd(a1, a3), t13m = csub(a1, a3);
        float2 it13m = make_float2(-t13m.y, t13m.x);    // i*(a1-a3)
        float2 w1 = tw[ps], w2 = tw[2 * ps], w3 = tw[3 * ps];
        y[4 * ps + q]         = cadd(t02p, t13p);
        y[4 * ps + s + q]     = cmulf(csub(t02m, it13m), w1);
        y[4 * ps + 2 * s + q] = cmulf(csub(t02p, t13p), w2);
        y[4 * ps + 3 * s + q] = cmulf(cadd(t02m, it13m), w3);
        __syncthreads();
        float2* t = x; x = y; y = t;
    }

    // Multiply by the (real, even) ramp filter
    #pragma unroll
    for (int e = 0; e < 4; ++e) {
        int i = tid + 256 * e;
        float f = filt[i];
        float2 c = x[i]; c.x *= f; c.y *= f; x[i] = c;
    }
    __syncthreads();

    // Inverse FFT: 5 radix-4 stages, conjugated twiddles
    #pragma unroll
    for (int stage = 0; stage < 5; ++stage) {
        const int s  = 1 << (2 * stage);
        const int q  = tid & (s - 1);
        const int ps = tid - q;
        float2 a0 = x[tid];
        float2 a1 = x[tid + 256];
        float2 a2 = x[tid + 512];
        float2 a3 = x[tid + 768];
        float2 t02p = cadd(a0, a2), t02m = csub(a0, a2);
        float2 t13p = cadd(a1, a3), t13m = csub(a1, a3);
        float2 it13m = make_float2(-t13m.y, t13m.x);
        float2 w1 = tw[ps], w2 = tw[2 * ps], w3 = tw[3 * ps];
        w1.y = -w1.y; w2.y = -w2.y; w3.y = -w3.y;
        y[4 * ps + q]         = cadd(t02p, t13p);
        y[4 * ps + s + q]     = cmulf(cadd(t02m, it13m), w1);
        y[4 * ps + 2 * s + q] = cmulf(csub(t02p, t13p), w2);
        y[4 * ps + 3 * s + q] = cmulf(csub(t02m, it13m), w3);
        __syncthreads();
        float2* t = x; x = y; y = t;
    }

    // Store fp16 (re,im) = filtered batches (2m, 2m+1) into u32 slot p=m&3.
    const float invN = 1.0f / (float)ND;
    const int g2 = m >> 2;
    const int p  = m & 3;
    unsigned int* ov = (unsigned int*)g_v;
    const size_t base_u = ((size_t)(g2 * NA + a) * ND) * 4;

    #pragma unroll
    for (int e = 0; e < 4; ++e) {
        int i = tid + 256 * e;
        float2 c = x[i];
        ov[base_u + (size_t)i * 4 + p] =
            h2_as_u32(__floats2half2_rn(c.x * invN, c.y * invN));
    }
}

// -------------------------------------------------------------------------
// Kernel 2: backprojection (R14 configuration — best measured: 553.9us).
// Warp-cooperative 16-bin v-windows, 2 angles per LDG (lanes 0-15: angle
// 2p, 16-31: angle 2p+1), magic-number floor, lerp = 2 HFMA2/word,
// ww = 1 - w via HSUB2. DEPTH-3 LDG pipeline, unpacked slot state
// (R15's 48-reg pack/unpack variant cost more ALU than it bought in
// occupancy: 596us vs 554us).
//
// Magic floor: fr = (t-0.5)+(2^23+2^22) rounds to i0' in {floor(t)-1,
// floor(t)}; w = t-i0' in [0,1] exact; window corner uses the same
// arithmetic, -1 margin -> idx in [0,11] <= 15, idx+1 <= 12; window
// [148,886] subset of [0,1023].
// -------------------------------------------------------------------------
__global__ __launch_bounds__(256, 4) void fbp_backproj_kernel(float* __restrict__ out)
{
    __shared__ float4 cs2[NA / 2];   // (c0,s0,c1,s1) per angle pair

    const int tid = threadIdx.x;
    for (int i = tid; i < NA / 2; i += 256) {
        float s0, c0, s1, c1;
        sincosf((PI_F / (float)NA) * (float)(2 * i),     &s0, &c0);
        sincosf((PI_F / (float)NA) * (float)(2 * i + 1), &s1, &c1);
        cs2[i] = make_float4(c0, s0, c1, s1);
    }
    __syncthreads();

    const float MAGIC = 12582912.0f;                     // 2^23 + 2^22
    const float Cm    = 0.5f * (float)(ND - 1) - 0.5f;   // C - 0.5

    const int wrp  = tid >> 5;
    const int lane = tid & 31;
    const int xb = (blockIdx.x << 4) + ((wrp & 1) << 3);
    const int yb = (blockIdx.y << 4) + ((wrp >> 1) << 2);
    const int x = xb + (lane & 7);
    const int y = yb + (lane >> 3);
    const float px  = (float)x - 0.5f * (float)(NW - 1);
    const float py  = (float)y - 0.5f * (float)(NH - 1);
    const float pxb = (float)xb - 0.5f * (float)(NW - 1);
    const float pyb = (float)yb - 0.5f * (float)(NH - 1);

    const int g2 = blockIdx.z;
    const uint4* __restrict__ vb = g_v + (size_t)g2 * NA * ND;
    const int lanehalf = lane >> 4;
    const int lanelow  = lane & 15;
    const int BM = 0x4B400000;                 // float bits of MAGIC
    const __half2 ONE2 = __float2half2_rn(1.0f);

    float acc[8];
    #pragma unroll
    for (int j = 0; j < 8; ++j) acc[j] = 0.0f;

    // ---- depth-3 pipeline state (slim: no q kept) ----
    int   b0s[3], b1s[3];
    uint4 rs[3];

#define PREFETCH(IDX, SLOT) do {                                               \
        int _p = (IDX); if (_p >= NA / 2) _p -= NA / 2;                        \
        float4 _q = cs2[_p];                                                   \
        float _pxm0 = (_q.x < 0.0f) ? pxb + 7.0f : pxb;                        \
        float _pxm1 = (_q.z < 0.0f) ? pxb + 7.0f : pxb;                        \
        int _bm0 = __float_as_int(__fadd_rn(fmaf(_pxm0, _q.x,                  \
                        fmaf(pyb, _q.y, Cm)), MAGIC));                         \
        int _bm1 = __float_as_int(__fadd_rn(fmaf(_pxm1, _q.z,                  \
                        fmaf(pyb, _q.w, Cm)), MAGIC));                         \
        int _ib = (lanehalf ? _bm1 : _bm0) - BM - 1;                           \
        rs[SLOT]  = vb[(2 * _p + lanehalf) * ND + _ib + lanelow];              \
        b0s[SLOT] = _bm0; b1s[SLOT] = _bm1;                                    \
    } while (0)

    PREFETCH(0, 0);
    PREFETCH(1, 1);
    PREFETCH(2, 2);

    for (int p = 0; p < NA / 2; p += 12) {       // 30 outer iterations
        __half2 h0 = __float2half2_rn(0.0f);
        __half2 h1 = h0, h2 = h0, h3 = h0;

        #pragma unroll
        for (int j = 0; j < 12; ++j) {
            const int slot = j % 3;              // compile-time (j literal)
            float4 q = cs2[p + j];               // re-read (1 LDS.128, bcast)
            int bm0 = b0s[slot], bm1 = b1s[slot];
            uint4 r = rs[slot];
            PREFETCH(p + j + 3, slot);

            // angle 2(p+j) (window lanes 0-15)
            {
                float ft = fmaf(px, q.x, fmaf(py, q.y, Cm));
                float fr = __fadd_rn(ft, MAGIC);
                float fi = __fsub_rn(fr, MAGIC);
                float d  = __fsub_rn(ft, fi);            // [-0.5, 0.5] exact
                __half2 w2  = __float2half2_rn(__fadd_rn(d, 0.5f));
                __half2 ww2 = __hsub2(ONE2, w2);         // 1-w (fma pipe)
                int s0i = __float_as_int(fr) - bm0 + 1;  // [0,11]
                int s1i = s0i + 1;

                __half2 vx = u32_as_h2(__shfl_sync(0xffffffffu, r.x, s0i));
                __half2 vy = u32_as_h2(__shfl_sync(0xffffffffu, r.y, s0i));
                __half2 vz = u32_as_h2(__shfl_sync(0xffffffffu, r.z, s0i));
                __half2 vw = u32_as_h2(__shfl_sync(0xffffffffu, r.w, s0i));
                __half2 ux = u32_as_h2(__shfl_sync(0xffffffffu, r.x, s1i));
                __half2 uy = u32_as_h2(__shfl_sync(0xffffffffu, r.y, s1i));
                __half2 uz = u32_as_h2(__shfl_sync(0xffffffffu, r.z, s1i));
                __half2 uw = u32_as_h2(__shfl_sync(0xffffffffu, r.w, s1i));

                h0 = __hfma2(ww2, vx, __hfma2(w2, ux, h0));
                h1 = __hfma2(ww2, vy, __hfma2(w2, uy, h1));
                h2 = __hfma2(ww2, vz, __hfma2(w2, uz, h2));
                h3 = __hfma2(ww2, vw, __hfma2(w2, uw, h3));
            }
            // angle 2(p+j)+1 (window lanes 16-31)
            {
                float ft = fmaf(px, q.z, fmaf(py, q.w, Cm));
                float fr = __fadd_rn(ft, MAGIC);
                float fi = __fsub_rn(fr, MAGIC);
                float d  = __fsub_rn(ft, fi);
                __half2 w2  = __float2half2_rn(__fadd_rn(d, 0.5f));
                __half2 ww2 = __hsub2(ONE2, w2);
                int s0i = __float_as_int(fr) - bm1 + 17; // [16,27]
                int s1i = s0i + 1;

                __half2 vx = u32_as_h2(__shfl_sync(0xffffffffu, r.x, s0i));
                __half2 vy = u32_as_h2(__shfl_sync(0xffffffffu, r.y, s0i));
                __half2 vz = u32_as_h2(__shfl_sync(0xffffffffu, r.z, s0i));
                __half2 vw = u32_as_h2(__shfl_sync(0xffffffffu, r.w, s0i));
                __half2 ux = u32_as_h2(__shfl_sync(0xffffffffu, r.x, s1i));
                __half2 uy = u32_as_h2(__shfl_sync(0xffffffffu, r.y, s1i));
                __half2 uz = u32_as_h2(__shfl_sync(0xffffffffu, r.z, s1i));
                __half2 uw = u32_as_h2(__shfl_sync(0xffffffffu, r.w, s1i));

                h0 = __hfma2(ww2, vx, __hfma2(w2, ux, h0));
                h1 = __hfma2(ww2, vy, __hfma2(w2, uy, h1));
                h2 = __hfma2(ww2, vz, __hfma2(w2, uz, h2));
                h3 = __hfma2(ww2, vw, __hfma2(w2, uw, h3));
            }

            if ((j & 3) == 3) {                  // flush every 4 pairs = 8 angles
                acc[0] += __low2float(h0);  acc[1] += __high2float(h0);
                acc[2] += __low2float(h1);  acc[3] += __high2float(h1);
                acc[4] += __low2float(h2);  acc[5] += __high2float(h2);
                acc[6] += __low2float(h3);  acc[7] += __high2float(h3);
                h0 = __float2half2_rn(0.0f);
                h1 = h0; h2 = h0; h3 = h0;
            }
        }
    }
#undef PREFETCH

    const float scale = PI_F / (float)NA;
    const size_t pix = (size_t)y * NW + x;
    const size_t HW = (size_t)NH * NW;
    float* dst = out + (size_t)(8 * g2) * HW + pix;
    #pragma unroll
    for (int j = 0; j < 8; ++j)
        dst[(size_t)j * HW] = acc[j] * scale;
}

extern "C" void kernel_launch(void* const* d_in, const int* in_sizes, int n_in,
                              void* d_out, int out_size)
{
    const float* sino = (const float*)d_in[0];   // (16, 720, 1024) fp32
    const float* filt = (const float*)d_in[1];   // (1024,) fp32
    float* out = (float*)d_out;                  // (16, 512, 512) fp32

    dim3 fgrid(NA, NB / 2);
    fbp_filter_kernel<<<fgrid, 256>>>(sino, filt);

    dim3 bgrid(NW / 16, NH / 16, 2);
    fbp_backproj_kernel<<<bgrid, 256>>>(out);
}